// round 1
// baseline (speedup 1.0000x reference)
#include <cuda_runtime.h>

#define T_DIM  4096
#define C_DIM  2048
#define NE_DIM 2048
#define S_CHUNKS 32
#define L_CHUNK  128

// ---------------- scratch (device globals: allocation-free) ----------------
__device__ float g_k[T_DIM * C_DIM];
__device__ float g_v[T_DIM * C_DIM];
__device__ float g_r[T_DIM * C_DIM];
__device__ float g_gated[T_DIM * C_DIM];
__device__ float g_carryA[S_CHUNKS * C_DIM];
__device__ float g_carryB[S_CHUNKS * C_DIM];
__device__ float g_scanA[S_CHUNKS * C_DIM];
__device__ float g_scanB[S_CHUNKS * C_DIM];

// ---------------- SGEMM: out[M,N] = A[M,K] @ W[K,N] ------------------------
// FUSE_MIX: A[m][k] = x[m][k]*mix[k] + x[m-1][k]*(1-mix[k])  (row -1 = zeros)
// BM=BN=128, BK=16, 256 threads, 8x8 microtile per thread.
template <bool FUSE_MIX>
__global__ __launch_bounds__(256, 2)
void sgemm_kernel(const float* __restrict__ X, const float* __restrict__ W,
                  const float* __restrict__ mix, float* __restrict__ out,
                  int M, int N, int K)
{
    __shared__ float As[16][132];   // padded, transposed: As[k][m]
    __shared__ float Bs[16][128];

    const int tid = threadIdx.x;
    const int m0 = blockIdx.y * 128;
    const int n0 = blockIdx.x * 128;
    const int tx = tid & 15;        // 0..15 -> N
    const int ty = tid >> 4;        // 0..15 -> M

    float acc[8][8];
#pragma unroll
    for (int i = 0; i < 8; i++)
#pragma unroll
        for (int j = 0; j < 8; j++) acc[i][j] = 0.f;

    for (int k0 = 0; k0 < K; k0 += 16) {
        // ---- A tile: 128 rows x 16 cols, 512 float4 loads / 256 threads ----
#pragma unroll
        for (int i = 0; i < 2; i++) {
            int idx = tid + i * 256;         // 0..511
            int ar  = idx >> 2;              // 0..127
            int ac  = (idx & 3) << 2;        // 0,4,8,12
            int gm  = m0 + ar;
            float4 x4 = *(const float4*)(X + (size_t)gm * K + k0 + ac);
            float4 a4;
            if (FUSE_MIX) {
                float4 mx = *(const float4*)(mix + k0 + ac);
                float4 xp = make_float4(0.f, 0.f, 0.f, 0.f);
                if (gm > 0)
                    xp = *(const float4*)(X + (size_t)(gm - 1) * K + k0 + ac);
                a4.x = x4.x * mx.x + xp.x * (1.f - mx.x);
                a4.y = x4.y * mx.y + xp.y * (1.f - mx.y);
                a4.z = x4.z * mx.z + xp.z * (1.f - mx.z);
                a4.w = x4.w * mx.w + xp.w * (1.f - mx.w);
            } else {
                a4 = x4;
            }
            As[ac + 0][ar] = a4.x;
            As[ac + 1][ar] = a4.y;
            As[ac + 2][ar] = a4.z;
            As[ac + 3][ar] = a4.w;
        }
        // ---- B tile: 16 rows x 128 cols ----
#pragma unroll
        for (int i = 0; i < 2; i++) {
            int idx = tid + i * 256;
            int br  = idx >> 5;              // 0..15
            int bc  = (idx & 31) << 2;       // 0..124
            *(float4*)&Bs[br][bc] =
                *(const float4*)(W + (size_t)(k0 + br) * N + n0 + bc);
        }
        __syncthreads();

#pragma unroll
        for (int kk = 0; kk < 16; kk++) {
            float ra[8], rb[8];
            *(float4*)&ra[0] = *(const float4*)&As[kk][ty * 8];
            *(float4*)&ra[4] = *(const float4*)&As[kk][ty * 8 + 4];
            *(float4*)&rb[0] = *(const float4*)&Bs[kk][tx * 8];
            *(float4*)&rb[4] = *(const float4*)&Bs[kk][tx * 8 + 4];
#pragma unroll
            for (int i = 0; i < 8; i++)
#pragma unroll
                for (int j = 0; j < 8; j++)
                    acc[i][j] += ra[i] * rb[j];
        }
        __syncthreads();
    }

#pragma unroll
    for (int i = 0; i < 8; i++) {
        int gm = m0 + ty * 8 + i;
        float* op = out + (size_t)gm * N + n0 + tx * 8;
        *(float4*)(op)     = make_float4(acc[i][0], acc[i][1], acc[i][2], acc[i][3]);
        *(float4*)(op + 4) = make_float4(acc[i][4], acc[i][5], acc[i][6], acc[i][7]);
    }
}

// ---------------- WKV chunked scan ------------------------------------------
// decay per step: d_c = exp(-q_c), q_c = exp(-exp(time_decay_c))
// A_{t+1} = d*A_t + e^{k_t} v_t ; wkv_t = (A_t + e^{u+k_t} v_t)/(B_t + e^{u+k_t})

__global__ void wkv_pass1(const float* __restrict__ tdecay)
{
    int s = blockIdx.x >> 3;                      // chunk 0..31
    int c = ((blockIdx.x & 7) << 8) + threadIdx.x;
    float q = __expf(-__expf(tdecay[c]));
    float d = __expf(-q);
    float A = 0.f, B = 0.f;
    int base = s * L_CHUNK;
    for (int j = 0; j < L_CHUNK; j++) {
        size_t off = (size_t)(base + j) * C_DIM + c;
        float e  = __expf(g_k[off]);
        float vv = g_v[off];
        A = d * A + e * vv;
        B = d * B + e;
    }
    g_carryA[s * C_DIM + c] = A;
    g_carryB[s * C_DIM + c] = B;
}

__global__ void wkv_pass2(const float* __restrict__ tdecay)
{
    int c = blockIdx.x * 256 + threadIdx.x;
    float q  = __expf(-__expf(tdecay[c]));
    float dL = __expf(-q * (float)L_CHUNK);
    float A = 0.f, B = 0.f;
    for (int s = 0; s < S_CHUNKS; s++) {
        g_scanA[s * C_DIM + c] = A;
        g_scanB[s * C_DIM + c] = B;
        A = dL * A + g_carryA[s * C_DIM + c];
        B = dL * B + g_carryB[s * C_DIM + c];
    }
}

__global__ void wkv_pass3(const float* __restrict__ tdecay,
                          const float* __restrict__ tfirst)
{
    int s = blockIdx.x >> 3;
    int c = ((blockIdx.x & 7) << 8) + threadIdx.x;
    float q  = __expf(-__expf(tdecay[c]));
    float d  = __expf(-q);
    float eu = __expf(tfirst[c]);
    float A = g_scanA[s * C_DIM + c];
    float B = g_scanB[s * C_DIM + c];
    int base = s * L_CHUNK;
    for (int j = 0; j < L_CHUNK; j++) {
        size_t off = (size_t)(base + j) * C_DIM + c;
        float kk = g_k[off];
        float vv = g_v[off];
        float rr = g_r[off];
        float e   = __expf(kk);
        float eue = eu * e;
        float wkv = (A + eue * vv) / (B + eue);
        float sr  = 1.f / (1.f + __expf(-rr));
        g_gated[off] = sr * wkv;
        A = d * A + e * vv;
        B = d * B + e;
    }
}

// ---------------- launch -----------------------------------------------------
extern "C" void kernel_launch(void* const* d_in, const int* in_sizes, int n_in,
                              void* d_out, int out_size)
{
    const float* x  = (const float*)d_in[0];
    const float* tf = (const float*)d_in[1];
    const float* td = (const float*)d_in[2];
    const float* mk = (const float*)d_in[3];
    const float* mv = (const float*)d_in[4];
    const float* mr = (const float*)d_in[5];
    const float* Wk = (const float*)d_in[6];
    const float* Wv = (const float*)d_in[7];
    const float* Wr = (const float*)d_in[8];
    const float* Wo = (const float*)d_in[9];
    float* out = (float*)d_out;

    float *pk, *pv, *pr, *pg;
    cudaGetSymbolAddress((void**)&pk, g_k);
    cudaGetSymbolAddress((void**)&pv, g_v);
    cudaGetSymbolAddress((void**)&pr, g_r);
    cudaGetSymbolAddress((void**)&pg, g_gated);

    dim3 block(256);
    dim3 gridQKV(C_DIM / 128, T_DIM / 128);   // (16, 32)

    // k, v, r projections with fused time-shift mixing
    sgemm_kernel<true><<<gridQKV, block>>>(x, Wk, mk, pk, T_DIM, C_DIM, NE_DIM);
    sgemm_kernel<true><<<gridQKV, block>>>(x, Wv, mv, pv, T_DIM, C_DIM, NE_DIM);
    sgemm_kernel<true><<<gridQKV, block>>>(x, Wr, mr, pr, T_DIM, C_DIM, NE_DIM);

    // WKV chunked linear scan + sigmoid(r) gating
    wkv_pass1<<<S_CHUNKS * (C_DIM / 256), block>>>(td);
    wkv_pass2<<<C_DIM / 256, block>>>(td);
    wkv_pass3<<<S_CHUNKS * (C_DIM / 256), block>>>(td, tf);

    // output projection
    dim3 gridO(NE_DIM / 128, T_DIM / 128);
    sgemm_kernel<false><<<gridO, block>>>(pg, Wo, nullptr, out, T_DIM, NE_DIM, C_DIM);
}

// round 3
// speedup vs baseline: 2.0244x; 2.0244x over previous
#include <cuda_runtime.h>
#include <cuda_bf16.h>
#include <cstdint>

#define T_DIM  4096
#define C_DIM  2048
#define K_DIM  2048
#define S_CHUNKS 32
#define L_CHUNK  128

#define KTILE  32
#define NKT    (K_DIM / KTILE)        // 64
#define ROWP   40                     // padded row length in bf16 (80 bytes)
#define SECT_BYTES (128 * ROWP * 2)   // 10240 per matrix section
#define STAGE_BYTES (4 * SECT_BYTES)  // Ah,Al,Bh,Bl = 40960
#define NSTAGE 3
#define SMEM_TOTAL (NSTAGE * STAGE_BYTES)

typedef __nv_bfloat16 bf16;

// ===================== PTX helpers =====================
__device__ __forceinline__ uint32_t smem_u32(const void* p) {
    uint32_t a;
    asm("{ .reg .u64 t; cvta.to.shared.u64 t, %1; cvt.u32.u64 %0, t; }" : "=r"(a) : "l"(p));
    return a;
}
__device__ __forceinline__ void cp16(uint32_t smem, const void* g) {
    asm volatile("cp.async.cg.shared.global [%0], [%1], 16;" :: "r"(smem), "l"(g));
}
#define CP_COMMIT() asm volatile("cp.async.commit_group;" ::: "memory")
#define CP_WAIT(n)  asm volatile("cp.async.wait_group %0;" :: "n"(n) : "memory")

__device__ __forceinline__ void ldsm4(uint32_t& r0, uint32_t& r1, uint32_t& r2, uint32_t& r3,
                                      uint32_t addr) {
    asm volatile("ldmatrix.sync.aligned.m8n8.x4.shared.b16 {%0,%1,%2,%3}, [%4];"
                 : "=r"(r0), "=r"(r1), "=r"(r2), "=r"(r3) : "r"(addr));
}
__device__ __forceinline__ void mma16816(float& c0, float& c1, float& c2, float& c3,
                                         uint32_t a0, uint32_t a1, uint32_t a2, uint32_t a3,
                                         uint32_t b0, uint32_t b1) {
    asm volatile("mma.sync.aligned.m16n8k16.row.col.f32.bf16.bf16.f32 "
                 "{%0,%1,%2,%3}, {%4,%5,%6,%7}, {%8,%9}, {%0,%1,%2,%3};"
                 : "+f"(c0), "+f"(c1), "+f"(c2), "+f"(c3)
                 : "r"(a0), "r"(a1), "r"(a2), "r"(a3), "r"(b0), "r"(b1));
}

// ===================== scratch =====================
__device__ float g_k[T_DIM * C_DIM];
__device__ float g_v[T_DIM * C_DIM];
__device__ float g_r[T_DIM * C_DIM];
__device__ float g_carryA[S_CHUNKS * C_DIM];
__device__ float g_carryB[S_CHUNKS * C_DIM];
__device__ float g_scanA[S_CHUNKS * C_DIM];
__device__ float g_scanB[S_CHUNKS * C_DIM];

__device__ bf16 g_axh[3][T_DIM * K_DIM];   // mixed activations hi
__device__ bf16 g_axl[3][T_DIM * K_DIM];   // lo
__device__ bf16 g_wth[4][C_DIM * K_DIM];   // W^T [N,K] hi
__device__ bf16 g_wtl[4][C_DIM * K_DIM];   // lo
__device__ bf16 g_gh[T_DIM * C_DIM];       // gated hi
__device__ bf16 g_gl[T_DIM * C_DIM];       // lo

// ===================== pre-pass: mix + split =====================
__device__ __forceinline__ uint32_t pack_hi2(float a, float b, float& ra, float& rb) {
    __nv_bfloat162 t;
    t.x = __float2bfloat16_rn(a); t.y = __float2bfloat16_rn(b);
    ra = a - __bfloat162float(t.x); rb = b - __bfloat162float(t.y);
    return *reinterpret_cast<uint32_t*>(&t);
}
__device__ __forceinline__ uint32_t pack_lo2(float a, float b) {
    __nv_bfloat162 t;
    t.x = __float2bfloat16_rn(a); t.y = __float2bfloat16_rn(b);
    return *reinterpret_cast<uint32_t*>(&t);
}

__global__ void mix_split(const float* __restrict__ x, const float* __restrict__ mk,
                          const float* __restrict__ mv, const float* __restrict__ mr)
{
    int idx = blockIdx.x * 256 + threadIdx.x;
    int m  = idx >> 9;
    int c4 = (idx & 511) << 2;
    size_t off = (size_t)m * C_DIM + c4;
    float4 xc = *(const float4*)(x + off);
    float4 xp = make_float4(0.f, 0.f, 0.f, 0.f);
    if (m > 0) xp = *(const float4*)(x + off - C_DIM);
    const float* mixes[3] = { mk, mv, mr };
#pragma unroll
    for (int p = 0; p < 3; p++) {
        float4 mx = *(const float4*)(mixes[p] + c4);
        float a0 = xc.x * mx.x + xp.x * (1.f - mx.x);
        float a1 = xc.y * mx.y + xp.y * (1.f - mx.y);
        float a2 = xc.z * mx.z + xp.z * (1.f - mx.z);
        float a3 = xc.w * mx.w + xp.w * (1.f - mx.w);
        float l0, l1, l2, l3;
        uint2 hi, lo;
        hi.x = pack_hi2(a0, a1, l0, l1);
        hi.y = pack_hi2(a2, a3, l2, l3);
        lo.x = pack_lo2(l0, l1);
        lo.y = pack_lo2(l2, l3);
        *(uint2*)(&g_axh[p][off]) = hi;
        *(uint2*)(&g_axl[p][off]) = lo;
    }
}

// ===================== pre-pass: weight transpose + split =====================
__global__ void wsplit(const float* __restrict__ W, int which)
{
    __shared__ float t[32][33];
    int n0 = blockIdx.x * 32, k0 = blockIdx.y * 32;
    int tx = threadIdx.x, ty = threadIdx.y;
#pragma unroll
    for (int i = 0; i < 32; i += 8)
        t[ty + i][tx] = W[(size_t)(k0 + ty + i) * C_DIM + n0 + tx];
    __syncthreads();
#pragma unroll
    for (int i = 0; i < 32; i += 8) {
        float a = t[tx][ty + i];
        bf16 h = __float2bfloat16_rn(a);
        size_t off = (size_t)(n0 + ty + i) * K_DIM + k0 + tx;
        g_wth[which][off] = h;
        g_wtl[which][off] = __float2bfloat16_rn(a - __bfloat162float(h));
    }
}

// ===================== HMMA GEMM =====================
// C[4096,2048] = (Ah+Al)[M,K] @ (Bh+Bl)[N,K]^T, 3-product bf16 split.
__device__ __forceinline__ void load_stage(
    uint32_t sb, int slot, int kt, int m0, int n0, int tid,
    const bf16* __restrict__ Ah, const bf16* __restrict__ Al,
    const bf16* __restrict__ Bh, const bf16* __restrict__ Bl)
{
    const int k0 = kt * KTILE;
    uint32_t base = sb + slot * STAGE_BYTES;
#pragma unroll
    for (int t = 0; t < 8; t++) {
        int id   = tid + t * 256;          // 0..2047
        int sect = id >> 9;                // Ah,Al,Bh,Bl
        int sid  = id & 511;
        int row  = sid >> 2;
        int ch   = (sid & 3) << 3;         // halves: 0,8,16,24
        uint32_t so = base + sect * SECT_BYTES + row * (ROWP * 2) + ch * 2;
        const bf16* src = (sect == 0) ? Ah : (sect == 1) ? Al : (sect == 2) ? Bh : Bl;
        int grow = ((sect < 2) ? m0 : n0) + row;
        cp16(so, src + (size_t)grow * K_DIM + k0 + ch);
    }
    CP_COMMIT();
}

__device__ __forceinline__ void gemm_body(
    const bf16* __restrict__ Ah, const bf16* __restrict__ Al,
    const bf16* __restrict__ Bh, const bf16* __restrict__ Bl,
    float* __restrict__ Cout)
{
    extern __shared__ __align__(128) char smem[];
    uint32_t sb = smem_u32(smem);
    const int tid = threadIdx.x;
    const int wid = tid >> 5, lane = tid & 31;
    const int warp_m = wid >> 2;           // 0..1
    const int warp_n = wid & 3;            // 0..3
    const int m0 = blockIdx.y * 128;
    const int n0 = blockIdx.x * 128;

    float acc[4][4][4];
#pragma unroll
    for (int i = 0; i < 4; i++)
#pragma unroll
        for (int j = 0; j < 4; j++)
#pragma unroll
            for (int q = 0; q < 4; q++) acc[i][j][q] = 0.f;

    load_stage(sb, 0, 0, m0, n0, tid, Ah, Al, Bh, Bl);
    load_stage(sb, 1, 1, m0, n0, tid, Ah, Al, Bh, Bl);

    const uint32_t lrow = lane & 15;
    const uint32_t lcol = (lane >> 4) << 3;   // 0 or 8 halves

    for (int kt = 0; kt < NKT; kt++) {
        const int s = kt % NSTAGE;
        CP_WAIT(1);
        __syncthreads();
        if (kt + 2 < NKT)
            load_stage(sb, (kt + 2) % NSTAGE, kt + 2, m0, n0, tid, Ah, Al, Bh, Bl);
        else
            CP_COMMIT();   // keep group counts aligned

        uint32_t stage = sb + s * STAGE_BYTES;
#pragma unroll
        for (int kk = 0; kk < 2; kk++) {
            uint32_t coff = (kk * 16 + lcol) * 2;
            uint32_t abase = stage + (warp_m * 64 + lrow) * (ROWP * 2) + coff;
            uint32_t bbase = stage + 2 * SECT_BYTES + (warp_n * 32 + lrow) * (ROWP * 2) + coff;

            uint32_t ah[4][4], al[4][4];
#pragma unroll
            for (int mi = 0; mi < 4; mi++) {
                uint32_t ra = abase + mi * 16 * (ROWP * 2);
                ldsm4(ah[mi][0], ah[mi][1], ah[mi][2], ah[mi][3], ra);
                ldsm4(al[mi][0], al[mi][1], al[mi][2], al[mi][3], ra + SECT_BYTES);
            }
            uint32_t bh[8], bl[8];
            ldsm4(bh[0], bh[1], bh[2], bh[3], bbase);
            ldsm4(bh[4], bh[5], bh[6], bh[7], bbase + 16 * (ROWP * 2));
            ldsm4(bl[0], bl[1], bl[2], bl[3], bbase + SECT_BYTES);
            ldsm4(bl[4], bl[5], bl[6], bl[7], bbase + 16 * (ROWP * 2) + SECT_BYTES);

#pragma unroll
            for (int mi = 0; mi < 4; mi++) {
#pragma unroll
                for (int nt = 0; nt < 4; nt++) {
                    int i0 = (nt >> 1) * 4 + (nt & 1);
                    float* c = acc[mi][nt];
                    mma16816(c[0], c[1], c[2], c[3],
                             ah[mi][0], ah[mi][1], ah[mi][2], ah[mi][3],
                             bh[i0], bh[i0 + 2]);
                    mma16816(c[0], c[1], c[2], c[3],
                             ah[mi][0], ah[mi][1], ah[mi][2], ah[mi][3],
                             bl[i0], bl[i0 + 2]);
                    mma16816(c[0], c[1], c[2], c[3],
                             al[mi][0], al[mi][1], al[mi][2], al[mi][3],
                             bh[i0], bh[i0 + 2]);
                }
            }
        }
        __syncthreads();
    }

    // epilogue: scattered float2 stores
    const int er = lane >> 2;
    const int ec = (lane & 3) * 2;
#pragma unroll
    for (int mi = 0; mi < 4; mi++) {
#pragma unroll
        for (int nt = 0; nt < 4; nt++) {
            int r = m0 + warp_m * 64 + mi * 16 + er;
            int c = n0 + warp_n * 32 + nt * 8 + ec;
            float* c0 = Cout + (size_t)r * 2048 + c;
            *(float2*)c0              = make_float2(acc[mi][nt][0], acc[mi][nt][1]);
            *(float2*)(c0 + 8 * 2048) = make_float2(acc[mi][nt][2], acc[mi][nt][3]);
        }
    }
}

__global__ void __launch_bounds__(256, 1) gemm_qkv()
{
    int p = blockIdx.z;
    float* C = (p == 0) ? g_k : (p == 1) ? g_v : g_r;
    gemm_body(g_axh[p], g_axl[p], g_wth[p], g_wtl[p], C);
}

__global__ void __launch_bounds__(256, 1) gemm_out(float* __restrict__ out)
{
    gemm_body(g_gh, g_gl, g_wth[3], g_wtl[3], out);
}

// ===================== WKV chunked scan =====================
__global__ void wkv_pass1(const float* __restrict__ tdecay)
{
    int s = blockIdx.x >> 3;
    int c = ((blockIdx.x & 7) << 8) + threadIdx.x;
    float q = __expf(-__expf(tdecay[c]));
    float d = __expf(-q);
    float A = 0.f, B = 0.f;
    int base = s * L_CHUNK;
    for (int j = 0; j < L_CHUNK; j++) {
        size_t off = (size_t)(base + j) * C_DIM + c;
        float e = __expf(g_k[off]);
        float vv = g_v[off];
        A = d * A + e * vv;
        B = d * B + e;
    }
    g_carryA[s * C_DIM + c] = A;
    g_carryB[s * C_DIM + c] = B;
}

__global__ void wkv_pass2(const float* __restrict__ tdecay)
{
    int c = blockIdx.x * 256 + threadIdx.x;
    float q = __expf(-__expf(tdecay[c]));
    float dL = __expf(-q * (float)L_CHUNK);
    float A = 0.f, B = 0.f;
    for (int s = 0; s < S_CHUNKS; s++) {
        g_scanA[s * C_DIM + c] = A;
        g_scanB[s * C_DIM + c] = B;
        A = dL * A + g_carryA[s * C_DIM + c];
        B = dL * B + g_carryB[s * C_DIM + c];
    }
}

__global__ void wkv_pass3(const float* __restrict__ tdecay,
                          const float* __restrict__ tfirst)
{
    int s = blockIdx.x >> 3;
    int c = ((blockIdx.x & 7) << 8) + threadIdx.x;
    float q = __expf(-__expf(tdecay[c]));
    float d = __expf(-q);
    float eu = __expf(tfirst[c]);
    float A = g_scanA[s * C_DIM + c];
    float B = g_scanB[s * C_DIM + c];
    int base = s * L_CHUNK;
    for (int j = 0; j < L_CHUNK; j++) {
        size_t off = (size_t)(base + j) * C_DIM + c;
        float kk = g_k[off];
        float vv = g_v[off];
        float rr = g_r[off];
        float e = __expf(kk);
        float eue = eu * e;
        float wkv = (A + eue * vv) / (B + eue);
        float sr = 1.f / (1.f + __expf(-rr));
        float g = sr * wkv;
        bf16 h = __float2bfloat16_rn(g);
        g_gh[off] = h;
        g_gl[off] = __float2bfloat16_rn(g - __bfloat162float(h));
        A = d * A + e * vv;
        B = d * B + e;
    }
}

// ===================== launch =====================
extern "C" void kernel_launch(void* const* d_in, const int* in_sizes, int n_in,
                              void* d_out, int out_size)
{
    const float* x  = (const float*)d_in[0];
    const float* tf = (const float*)d_in[1];
    const float* td = (const float*)d_in[2];
    const float* mk = (const float*)d_in[3];
    const float* mv = (const float*)d_in[4];
    const float* mr = (const float*)d_in[5];
    const float* Wk = (const float*)d_in[6];
    const float* Wv = (const float*)d_in[7];
    const float* Wr = (const float*)d_in[8];
    const float* Wo = (const float*)d_in[9];
    float* out = (float*)d_out;

    cudaFuncSetAttribute(gemm_qkv, cudaFuncAttributeMaxDynamicSharedMemorySize, SMEM_TOTAL);
    cudaFuncSetAttribute(gemm_out, cudaFuncAttributeMaxDynamicSharedMemorySize, SMEM_TOTAL);

    mix_split<<<(T_DIM * C_DIM / 4) / 256, 256>>>(x, mk, mv, mr);
    dim3 wgrid(C_DIM / 32, K_DIM / 32), wblk(32, 8);
    wsplit<<<wgrid, wblk>>>(Wk, 0);
    wsplit<<<wgrid, wblk>>>(Wv, 1);
    wsplit<<<wgrid, wblk>>>(Wr, 2);
    wsplit<<<wgrid, wblk>>>(Wo, 3);

    dim3 gqkv(C_DIM / 128, T_DIM / 128, 3);   // (16, 32, 3)
    gemm_qkv<<<gqkv, 256, SMEM_TOTAL>>>();

    wkv_pass1<<<S_CHUNKS * (C_DIM / 256), 256>>>(td);
    wkv_pass2<<<C_DIM / 256, 256>>>(td);
    wkv_pass3<<<S_CHUNKS * (C_DIM / 256), 256>>>(td, tf);

    dim3 go(C_DIM / 128, T_DIM / 128);
    gemm_out<<<go, 256, SMEM_TOTAL>>>(out);
}

// round 4
// speedup vs baseline: 2.2700x; 1.1213x over previous
#include <cuda_runtime.h>
#include <cuda_bf16.h>
#include <cstdint>

#define T_DIM  4096
#define C_DIM  2048
#define K_DIM  2048
#define S_CHUNKS 32
#define L_CHUNK  128

#define KTILE  64
#define NKT    (K_DIM / KTILE)        // 32
#define ROWP   72                     // padded row length in bf16 (144 B)
#define SECT_BYTES (128 * ROWP * 2)   // 18432 per matrix section
#define STAGE_BYTES (4 * SECT_BYTES)  // Ah,Al,Bh,Bl = 73728
#define NSTAGE 3
#define SMEM_TOTAL (NSTAGE * STAGE_BYTES)   // 221184

typedef __nv_bfloat16 bf16;

// ===================== PTX helpers =====================
__device__ __forceinline__ uint32_t smem_u32(const void* p) {
    uint32_t a;
    asm("{ .reg .u64 t; cvta.to.shared.u64 t, %1; cvt.u32.u64 %0, t; }" : "=r"(a) : "l"(p));
    return a;
}
__device__ __forceinline__ void cp16(uint32_t smem, const void* g) {
    asm volatile("cp.async.cg.shared.global [%0], [%1], 16;" :: "r"(smem), "l"(g));
}
#define CP_COMMIT() asm volatile("cp.async.commit_group;" ::: "memory")
#define CP_WAIT(n)  asm volatile("cp.async.wait_group %0;" :: "n"(n) : "memory")

__device__ __forceinline__ void ldsm4(uint32_t& r0, uint32_t& r1, uint32_t& r2, uint32_t& r3,
                                      uint32_t addr) {
    asm volatile("ldmatrix.sync.aligned.m8n8.x4.shared.b16 {%0,%1,%2,%3}, [%4];"
                 : "=r"(r0), "=r"(r1), "=r"(r2), "=r"(r3) : "r"(addr));
}
__device__ __forceinline__ void mma16816(float& c0, float& c1, float& c2, float& c3,
                                         uint32_t a0, uint32_t a1, uint32_t a2, uint32_t a3,
                                         uint32_t b0, uint32_t b1) {
    asm volatile("mma.sync.aligned.m16n8k16.row.col.f32.bf16.bf16.f32 "
                 "{%0,%1,%2,%3}, {%4,%5,%6,%7}, {%8,%9}, {%0,%1,%2,%3};"
                 : "+f"(c0), "+f"(c1), "+f"(c2), "+f"(c3)
                 : "r"(a0), "r"(a1), "r"(a2), "r"(a3), "r"(b0), "r"(b1));
}

// ===================== scratch =====================
__device__ float g_k[T_DIM * C_DIM];
__device__ float g_v[T_DIM * C_DIM];
__device__ float g_r[T_DIM * C_DIM];
__device__ float g_carryA[S_CHUNKS * C_DIM];
__device__ float g_carryB[S_CHUNKS * C_DIM];
__device__ float g_scanA[S_CHUNKS * C_DIM];
__device__ float g_scanB[S_CHUNKS * C_DIM];

__device__ bf16 g_axh[3][T_DIM * K_DIM];
__device__ bf16 g_axl[3][T_DIM * K_DIM];
__device__ bf16 g_wth[4][C_DIM * K_DIM];
__device__ bf16 g_wtl[4][C_DIM * K_DIM];
__device__ bf16 g_gh[T_DIM * C_DIM];
__device__ bf16 g_gl[T_DIM * C_DIM];

// ===================== pre-pass: mix + split =====================
__device__ __forceinline__ uint32_t pack_hi2(float a, float b, float& ra, float& rb) {
    __nv_bfloat162 t;
    t.x = __float2bfloat16_rn(a); t.y = __float2bfloat16_rn(b);
    ra = a - __bfloat162float(t.x); rb = b - __bfloat162float(t.y);
    return *reinterpret_cast<uint32_t*>(&t);
}
__device__ __forceinline__ uint32_t pack_lo2(float a, float b) {
    __nv_bfloat162 t;
    t.x = __float2bfloat16_rn(a); t.y = __float2bfloat16_rn(b);
    return *reinterpret_cast<uint32_t*>(&t);
}

__global__ void mix_split(const float* __restrict__ x, const float* __restrict__ mk,
                          const float* __restrict__ mv, const float* __restrict__ mr)
{
    int idx = blockIdx.x * 256 + threadIdx.x;
    int m  = idx >> 9;
    int c4 = (idx & 511) << 2;
    size_t off = (size_t)m * C_DIM + c4;
    float4 xc = *(const float4*)(x + off);
    float4 xp = make_float4(0.f, 0.f, 0.f, 0.f);
    if (m > 0) xp = *(const float4*)(x + off - C_DIM);
    const float* mixes[3] = { mk, mv, mr };
#pragma unroll
    for (int p = 0; p < 3; p++) {
        float4 mx = *(const float4*)(mixes[p] + c4);
        float a0 = xc.x * mx.x + xp.x * (1.f - mx.x);
        float a1 = xc.y * mx.y + xp.y * (1.f - mx.y);
        float a2 = xc.z * mx.z + xp.z * (1.f - mx.z);
        float a3 = xc.w * mx.w + xp.w * (1.f - mx.w);
        float l0, l1, l2, l3;
        uint2 hi, lo;
        hi.x = pack_hi2(a0, a1, l0, l1);
        hi.y = pack_hi2(a2, a3, l2, l3);
        lo.x = pack_lo2(l0, l1);
        lo.y = pack_lo2(l2, l3);
        *(uint2*)(&g_axh[p][off]) = hi;
        *(uint2*)(&g_axl[p][off]) = lo;
    }
}

// ===================== pre-pass: weight transpose + split (pair) =====================
__global__ void wsplit_pair(const float* __restrict__ W0, const float* __restrict__ W1,
                            int base)
{
    __shared__ float t[32][33];
    const float* W = (blockIdx.z == 0) ? W0 : W1;
    int which = base + blockIdx.z;
    int n0 = blockIdx.x * 32, k0 = blockIdx.y * 32;
    int tx = threadIdx.x, ty = threadIdx.y;
#pragma unroll
    for (int i = 0; i < 32; i += 8)
        t[ty + i][tx] = W[(size_t)(k0 + ty + i) * C_DIM + n0 + tx];
    __syncthreads();
#pragma unroll
    for (int i = 0; i < 32; i += 8) {
        float a = t[tx][ty + i];
        bf16 h = __float2bfloat16_rn(a);
        size_t off = (size_t)(n0 + ty + i) * K_DIM + k0 + tx;
        g_wth[which][off] = h;
        g_wtl[which][off] = __float2bfloat16_rn(a - __bfloat162float(h));
    }
}

// ===================== HMMA GEMM =====================
__device__ __forceinline__ void load_stage(
    uint32_t sb, int slot, int kt, int m0, int n0, int tid,
    const bf16* __restrict__ Ah, const bf16* __restrict__ Al,
    const bf16* __restrict__ Bh, const bf16* __restrict__ Bl)
{
    const int k0 = kt * KTILE;
    uint32_t base = sb + slot * STAGE_BYTES;
#pragma unroll
    for (int t = 0; t < 16; t++) {
        int id   = tid + t * 256;          // 0..4095
        int sect = id >> 10;               // Ah,Al,Bh,Bl
        int sid  = id & 1023;
        int row  = sid >> 3;
        int ch   = (sid & 7) << 3;         // bf16 units: 0,8,...,56
        uint32_t so = base + sect * SECT_BYTES + row * (ROWP * 2) + ch * 2;
        const bf16* src = (sect == 0) ? Ah : (sect == 1) ? Al : (sect == 2) ? Bh : Bl;
        int grow = ((sect < 2) ? m0 : n0) + row;
        cp16(so, src + (size_t)grow * K_DIM + k0 + ch);
    }
    CP_COMMIT();
}

__device__ __forceinline__ void gemm_body(
    const bf16* __restrict__ Ah, const bf16* __restrict__ Al,
    const bf16* __restrict__ Bh, const bf16* __restrict__ Bl,
    float* __restrict__ Cout)
{
    extern __shared__ __align__(128) char smem[];
    uint32_t sb = smem_u32(smem);
    const int tid = threadIdx.x;
    const int wid = tid >> 5, lane = tid & 31;
    const int warp_m = wid >> 2;           // 0..1
    const int warp_n = wid & 3;            // 0..3
    const int m0 = blockIdx.y * 128;
    const int n0 = blockIdx.x * 128;

    float acc[4][4][4];
#pragma unroll
    for (int i = 0; i < 4; i++)
#pragma unroll
        for (int j = 0; j < 4; j++)
#pragma unroll
            for (int q = 0; q < 4; q++) acc[i][j][q] = 0.f;

    load_stage(sb, 0, 0, m0, n0, tid, Ah, Al, Bh, Bl);
    load_stage(sb, 1, 1, m0, n0, tid, Ah, Al, Bh, Bl);

    const uint32_t lrow = lane & 15;
    const uint32_t lcol = (lane >> 4) << 3;   // 0 or 8 (bf16 units)

    for (int kt = 0; kt < NKT; kt++) {
        const int s = kt % NSTAGE;
        CP_WAIT(1);
        __syncthreads();
        if (kt + 2 < NKT)
            load_stage(sb, (kt + 2) % NSTAGE, kt + 2, m0, n0, tid, Ah, Al, Bh, Bl);
        else
            CP_COMMIT();   // keep group bookkeeping monotone

        uint32_t stage = sb + s * STAGE_BYTES;
#pragma unroll
        for (int kk = 0; kk < 4; kk++) {
            uint32_t coff = (kk * 16 + lcol) * 2;
            uint32_t abase = stage + (warp_m * 64 + lrow) * (ROWP * 2) + coff;
            uint32_t bbase = stage + 2 * SECT_BYTES + (warp_n * 32 + lrow) * (ROWP * 2) + coff;

            uint32_t ah[4][4], al[4][4];
#pragma unroll
            for (int mi = 0; mi < 4; mi++) {
                uint32_t ra = abase + mi * 16 * (ROWP * 2);
                ldsm4(ah[mi][0], ah[mi][1], ah[mi][2], ah[mi][3], ra);
                ldsm4(al[mi][0], al[mi][1], al[mi][2], al[mi][3], ra + SECT_BYTES);
            }
            uint32_t bh[8], bl[8];
            ldsm4(bh[0], bh[1], bh[2], bh[3], bbase);
            ldsm4(bh[4], bh[5], bh[6], bh[7], bbase + 16 * (ROWP * 2));
            ldsm4(bl[0], bl[1], bl[2], bl[3], bbase + SECT_BYTES);
            ldsm4(bl[4], bl[5], bl[6], bl[7], bbase + 16 * (ROWP * 2) + SECT_BYTES);

#pragma unroll
            for (int mi = 0; mi < 4; mi++) {
#pragma unroll
                for (int nt = 0; nt < 4; nt++) {
                    int i0 = (nt >> 1) * 4 + (nt & 1);
                    float* c = acc[mi][nt];
                    mma16816(c[0], c[1], c[2], c[3],
                             ah[mi][0], ah[mi][1], ah[mi][2], ah[mi][3],
                             bh[i0], bh[i0 + 2]);
                    mma16816(c[0], c[1], c[2], c[3],
                             ah[mi][0], ah[mi][1], ah[mi][2], ah[mi][3],
                             bl[i0], bl[i0 + 2]);
                    mma16816(c[0], c[1], c[2], c[3],
                             al[mi][0], al[mi][1], al[mi][2], al[mi][3],
                             bh[i0], bh[i0 + 2]);
                }
            }
        }
    }

    const int er = lane >> 2;
    const int ec = (lane & 3) * 2;
#pragma unroll
    for (int mi = 0; mi < 4; mi++) {
#pragma unroll
        for (int nt = 0; nt < 4; nt++) {
            int r = m0 + warp_m * 64 + mi * 16 + er;
            int c = n0 + warp_n * 32 + nt * 8 + ec;
            float* c0 = Cout + (size_t)r * 2048 + c;
            *(float2*)c0              = make_float2(acc[mi][nt][0], acc[mi][nt][1]);
            *(float2*)(c0 + 8 * 2048) = make_float2(acc[mi][nt][2], acc[mi][nt][3]);
        }
    }
}

__global__ void __launch_bounds__(256, 1) gemm_qkv()
{
    int p = blockIdx.z;
    float* C = (p == 0) ? g_k : (p == 1) ? g_v : g_r;
    gemm_body(g_axh[p], g_axl[p], g_wth[p], g_wtl[p], C);
}

__global__ void __launch_bounds__(256, 1) gemm_out(float* __restrict__ out)
{
    gemm_body(g_gh, g_gl, g_wth[3], g_wtl[3], out);
}

// ===================== WKV chunked scan =====================
__global__ void wkv_pass1(const float* __restrict__ tdecay)
{
    int s = blockIdx.x >> 3;
    int c = ((blockIdx.x & 7) << 8) + threadIdx.x;
    float q = __expf(-__expf(tdecay[c]));
    float d = __expf(-q);
    float A = 0.f, B = 0.f;
    int base = s * L_CHUNK;
    for (int j = 0; j < L_CHUNK; j++) {
        size_t off = (size_t)(base + j) * C_DIM + c;
        float e = __expf(g_k[off]);
        float vv = g_v[off];
        A = d * A + e * vv;
        B = d * B + e;
    }
    g_carryA[s * C_DIM + c] = A;
    g_carryB[s * C_DIM + c] = B;
}

__global__ void wkv_pass2(const float* __restrict__ tdecay)
{
    int c = blockIdx.x * 256 + threadIdx.x;
    float q = __expf(-__expf(tdecay[c]));
    float dL = __expf(-q * (float)L_CHUNK);
    float A = 0.f, B = 0.f;
    for (int s = 0; s < S_CHUNKS; s++) {
        g_scanA[s * C_DIM + c] = A;
        g_scanB[s * C_DIM + c] = B;
        A = dL * A + g_carryA[s * C_DIM + c];
        B = dL * B + g_carryB[s * C_DIM + c];
    }
}

__global__ void wkv_pass3(const float* __restrict__ tdecay,
                          const float* __restrict__ tfirst)
{
    int s = blockIdx.x >> 3;
    int c = ((blockIdx.x & 7) << 8) + threadIdx.x;
    float q = __expf(-__expf(tdecay[c]));
    float d = __expf(-q);
    float eu = __expf(tfirst[c]);
    float A = g_scanA[s * C_DIM + c];
    float B = g_scanB[s * C_DIM + c];
    int base = s * L_CHUNK;
    for (int j = 0; j < L_CHUNK; j++) {
        size_t off = (size_t)(base + j) * C_DIM + c;
        float kk = g_k[off];
        float vv = g_v[off];
        float rr = g_r[off];
        float e = __expf(kk);
        float eue = eu * e;
        float wkv = (A + eue * vv) / (B + eue);
        float sr = 1.f / (1.f + __expf(-rr));
        float g = sr * wkv;
        bf16 h = __float2bfloat16_rn(g);
        g_gh[off] = h;
        g_gl[off] = __float2bfloat16_rn(g - __bfloat162float(h));
        A = d * A + e * vv;
        B = d * B + e;
    }
}

// ===================== launch =====================
extern "C" void kernel_launch(void* const* d_in, const int* in_sizes, int n_in,
                              void* d_out, int out_size)
{
    const float* x  = (const float*)d_in[0];
    const float* tf = (const float*)d_in[1];
    const float* td = (const float*)d_in[2];
    const float* mk = (const float*)d_in[3];
    const float* mv = (const float*)d_in[4];
    const float* mr = (const float*)d_in[5];
    const float* Wk = (const float*)d_in[6];
    const float* Wv = (const float*)d_in[7];
    const float* Wr = (const float*)d_in[8];
    const float* Wo = (const float*)d_in[9];
    float* out = (float*)d_out;

    cudaFuncSetAttribute(gemm_qkv, cudaFuncAttributeMaxDynamicSharedMemorySize, SMEM_TOTAL);
    cudaFuncSetAttribute(gemm_out, cudaFuncAttributeMaxDynamicSharedMemorySize, SMEM_TOTAL);

    // 1: mix + split
    mix_split<<<(T_DIM * C_DIM / 4) / 256, 256>>>(x, mk, mv, mr);
    // 2,3: weight transpose + split
    dim3 wgrid(C_DIM / 32, K_DIM / 32, 2), wblk(32, 8);
    wsplit_pair<<<wgrid, wblk>>>(Wk, Wv, 0);
    wsplit_pair<<<wgrid, wblk>>>(Wr, Wo, 2);

    // 4: fused k/v/r projections  (profiler captures this launch)
    dim3 gqkv(C_DIM / 128, T_DIM / 128, 3);
    gemm_qkv<<<gqkv, 256, SMEM_TOTAL>>>();

    // 5-7: WKV scan + gate
    wkv_pass1<<<S_CHUNKS * (C_DIM / 256), 256>>>(td);
    wkv_pass2<<<C_DIM / 256, 256>>>(td);
    wkv_pass3<<<S_CHUNKS * (C_DIM / 256), 256>>>(td, tf);

    // 8: output projection
    dim3 go(C_DIM / 128, T_DIM / 128);
    gemm_out<<<go, 256, SMEM_TOTAL>>>(out);
}

// round 5
// speedup vs baseline: 3.1833x; 1.4023x over previous
#include <cuda_runtime.h>
#include <cuda_fp16.h>
#include <cstdint>

#define T_DIM  4096
#define C_DIM  2048
#define K_DIM  2048
#define S_CHUNKS 32
#define L_CHUNK  128

#define KTILE  64
#define NKT    (K_DIM / KTILE)        // 32
#define ROWP   72                     // padded row length in fp16 (144 B)
#define SECT_BYTES (128 * ROWP * 2)   // 18432 per section
#define STAGE_BYTES (3 * SECT_BYTES)  // Ah, Al, B = 55296
#define NSTAGE 4
#define SMEM_TOTAL (NSTAGE * STAGE_BYTES)   // 221184 (216KB)

typedef __half f16;

// ===================== PTX helpers =====================
__device__ __forceinline__ uint32_t smem_u32(const void* p) {
    uint32_t a;
    asm("{ .reg .u64 t; cvta.to.shared.u64 t, %1; cvt.u32.u64 %0, t; }" : "=r"(a) : "l"(p));
    return a;
}
__device__ __forceinline__ void cp16(uint32_t smem, const void* g) {
    asm volatile("cp.async.cg.shared.global [%0], [%1], 16;" :: "r"(smem), "l"(g));
}
#define CP_COMMIT() asm volatile("cp.async.commit_group;" ::: "memory")
#define CP_WAIT(n)  asm volatile("cp.async.wait_group %0;" :: "n"(n) : "memory")

__device__ __forceinline__ void ldsm4(uint32_t& r0, uint32_t& r1, uint32_t& r2, uint32_t& r3,
                                      uint32_t addr) {
    asm volatile("ldmatrix.sync.aligned.m8n8.x4.shared.b16 {%0,%1,%2,%3}, [%4];"
                 : "=r"(r0), "=r"(r1), "=r"(r2), "=r"(r3) : "r"(addr));
}
__device__ __forceinline__ void mma16816(float& c0, float& c1, float& c2, float& c3,
                                         uint32_t a0, uint32_t a1, uint32_t a2, uint32_t a3,
                                         uint32_t b0, uint32_t b1) {
    asm volatile("mma.sync.aligned.m16n8k16.row.col.f32.f16.f16.f32 "
                 "{%0,%1,%2,%3}, {%4,%5,%6,%7}, {%8,%9}, {%0,%1,%2,%3};"
                 : "+f"(c0), "+f"(c1), "+f"(c2), "+f"(c3)
                 : "r"(a0), "r"(a1), "r"(a2), "r"(a3), "r"(b0), "r"(b1));
}

// ===================== scratch =====================
__device__ float g_k[T_DIM * C_DIM];
__device__ float g_v[T_DIM * C_DIM];
__device__ float g_r[T_DIM * C_DIM];
__device__ float g_carryA[S_CHUNKS * C_DIM];
__device__ float g_carryB[S_CHUNKS * C_DIM];
__device__ float g_scanA[S_CHUNKS * C_DIM];
__device__ float g_scanB[S_CHUNKS * C_DIM];

__device__ f16 g_axh[3][T_DIM * K_DIM];   // mixed activations hi
__device__ f16 g_axl[3][T_DIM * K_DIM];   // lo (fp16 residual)
__device__ f16 g_wt[4][C_DIM * K_DIM];    // W^T [N,K] single fp16
__device__ f16 g_gh[T_DIM * C_DIM];       // gated hi
__device__ f16 g_gl[T_DIM * C_DIM];       // gated lo

// ===================== pre-pass: mix + fp16 hi/lo split =====================
__global__ void mix_split(const float* __restrict__ x, const float* __restrict__ mk,
                          const float* __restrict__ mv, const float* __restrict__ mr)
{
    int idx = blockIdx.x * 256 + threadIdx.x;
    int m  = idx >> 9;
    int c4 = (idx & 511) << 2;
    size_t off = (size_t)m * C_DIM + c4;
    float4 xc = *(const float4*)(x + off);
    float4 xp = make_float4(0.f, 0.f, 0.f, 0.f);
    if (m > 0) xp = *(const float4*)(x + off - C_DIM);
    const float* mixes[3] = { mk, mv, mr };
#pragma unroll
    for (int p = 0; p < 3; p++) {
        float4 mx = *(const float4*)(mixes[p] + c4);
        float a[4];
        a[0] = xc.x * mx.x + xp.x * (1.f - mx.x);
        a[1] = xc.y * mx.y + xp.y * (1.f - mx.y);
        a[2] = xc.z * mx.z + xp.z * (1.f - mx.z);
        a[3] = xc.w * mx.w + xp.w * (1.f - mx.w);
        f16 h[4], l[4];
#pragma unroll
        for (int q = 0; q < 4; q++) {
            h[q] = __float2half_rn(a[q]);
            l[q] = __float2half_rn(a[q] - __half2float(h[q]));
        }
        *(uint2*)(&g_axh[p][off]) = *(uint2*)h;
        *(uint2*)(&g_axl[p][off]) = *(uint2*)l;
    }
}

// ===================== pre-pass: weight transpose to fp16 [N,K] =====================
__global__ void wsplit_pair(const float* __restrict__ W0, const float* __restrict__ W1,
                            int base)
{
    __shared__ float t[32][33];
    const float* W = (blockIdx.z == 0) ? W0 : W1;
    int which = base + blockIdx.z;
    int n0 = blockIdx.x * 32, k0 = blockIdx.y * 32;
    int tx = threadIdx.x, ty = threadIdx.y;
#pragma unroll
    for (int i = 0; i < 32; i += 8)
        t[ty + i][tx] = W[(size_t)(k0 + ty + i) * C_DIM + n0 + tx];
    __syncthreads();
#pragma unroll
    for (int i = 0; i < 32; i += 8)
        g_wt[which][(size_t)(n0 + ty + i) * K_DIM + k0 + tx] =
            __float2half_rn(t[tx][ty + i]);
}

// ===================== HMMA GEMM (fp16 2-product) =====================
// C[4096,2048] = (Ah+Al)[M,K] @ B[N,K]^T
__device__ __forceinline__ void load_stage(
    uint32_t sb, int slot, int kt, int m0, int n0, int tid,
    const f16* __restrict__ Ah, const f16* __restrict__ Al, const f16* __restrict__ B)
{
    const int k0 = kt * KTILE;
    uint32_t base = sb + slot * STAGE_BYTES;
#pragma unroll
    for (int t = 0; t < 6; t++) {
        int id   = tid + t * 512;          // 0..3071
        int sect = id >> 10;               // 0:Ah 1:Al 2:B
        int sid  = id & 1023;
        int row  = sid >> 3;
        int ch   = (sid & 7) << 3;         // fp16 units: 0..56
        uint32_t so = base + sect * SECT_BYTES + row * (ROWP * 2) + ch * 2;
        const f16* src = (sect == 0) ? Ah : (sect == 1) ? Al : B;
        int grow = ((sect < 2) ? m0 : n0) + row;
        cp16(so, src + (size_t)grow * K_DIM + k0 + ch);
    }
    CP_COMMIT();
}

__device__ __forceinline__ void gemm_body(
    const f16* __restrict__ Ah, const f16* __restrict__ Al,
    const f16* __restrict__ B, float* __restrict__ Cout)
{
    extern __shared__ __align__(128) char smem[];
    uint32_t sb = smem_u32(smem);
    const int tid = threadIdx.x;
    const int wid = tid >> 5, lane = tid & 31;
    const int warp_m = wid >> 2;           // 0..3 (32 rows each)
    const int warp_n = wid & 3;            // 0..3 (32 cols each)
    const int m0 = blockIdx.y * 128;
    const int n0 = blockIdx.x * 128;

    float acc[2][4][4];
#pragma unroll
    for (int i = 0; i < 2; i++)
#pragma unroll
        for (int j = 0; j < 4; j++)
#pragma unroll
            for (int q = 0; q < 4; q++) acc[i][j][q] = 0.f;

    load_stage(sb, 0, 0, m0, n0, tid, Ah, Al, B);
    load_stage(sb, 1, 1, m0, n0, tid, Ah, Al, B);
    load_stage(sb, 2, 2, m0, n0, tid, Ah, Al, B);

    const uint32_t lrow = lane & 15;
    const uint32_t lcol = (lane >> 4) << 3;

    for (int kt = 0; kt < NKT; kt++) {
        const int s = kt & 3;
        CP_WAIT(2);
        __syncthreads();
        if (kt + 3 < NKT)
            load_stage(sb, (kt + 3) & 3, kt + 3, m0, n0, tid, Ah, Al, B);
        else
            CP_COMMIT();

        uint32_t stage = sb + s * STAGE_BYTES;
#pragma unroll
        for (int kk = 0; kk < 4; kk++) {
            uint32_t coff = (kk * 16 + lcol) * 2;
            uint32_t abase = stage + (warp_m * 32 + lrow) * (ROWP * 2) + coff;
            uint32_t bbase = stage + 2 * SECT_BYTES + (warp_n * 32 + lrow) * (ROWP * 2) + coff;

            uint32_t ah[2][4], al[2][4], b[8];
#pragma unroll
            for (int mi = 0; mi < 2; mi++) {
                uint32_t ra = abase + mi * 16 * (ROWP * 2);
                ldsm4(ah[mi][0], ah[mi][1], ah[mi][2], ah[mi][3], ra);
                ldsm4(al[mi][0], al[mi][1], al[mi][2], al[mi][3], ra + SECT_BYTES);
            }
            ldsm4(b[0], b[1], b[2], b[3], bbase);
            ldsm4(b[4], b[5], b[6], b[7], bbase + 16 * (ROWP * 2));

#pragma unroll
            for (int mi = 0; mi < 2; mi++) {
#pragma unroll
                for (int nt = 0; nt < 4; nt++) {
                    int i0 = (nt >> 1) * 4 + (nt & 1);
                    float* c = acc[mi][nt];
                    mma16816(c[0], c[1], c[2], c[3],
                             ah[mi][0], ah[mi][1], ah[mi][2], ah[mi][3],
                             b[i0], b[i0 + 2]);
                    mma16816(c[0], c[1], c[2], c[3],
                             al[mi][0], al[mi][1], al[mi][2], al[mi][3],
                             b[i0], b[i0 + 2]);
                }
            }
        }
    }

    const int er = lane >> 2;
    const int ec = (lane & 3) * 2;
#pragma unroll
    for (int mi = 0; mi < 2; mi++) {
#pragma unroll
        for (int nt = 0; nt < 4; nt++) {
            int r = m0 + warp_m * 32 + mi * 16 + er;
            int c = n0 + warp_n * 32 + nt * 8 + ec;
            float* c0 = Cout + (size_t)r * 2048 + c;
            *(float2*)c0              = make_float2(acc[mi][nt][0], acc[mi][nt][1]);
            *(float2*)(c0 + 8 * 2048) = make_float2(acc[mi][nt][2], acc[mi][nt][3]);
        }
    }
}

__global__ void __launch_bounds__(512, 1) gemm_qkv()
{
    int p = blockIdx.z;
    float* C = (p == 0) ? g_k : (p == 1) ? g_v : g_r;
    gemm_body(g_axh[p], g_axl[p], g_wt[p], C);
}

__global__ void __launch_bounds__(512, 1) gemm_out(float* __restrict__ out)
{
    gemm_body(g_gh, g_gl, g_wt[3], out);
}

// ===================== WKV chunked scan =====================
__global__ void wkv_pass1(const float* __restrict__ tdecay)
{
    int s = blockIdx.x >> 3;
    int c = ((blockIdx.x & 7) << 8) + threadIdx.x;
    float q = __expf(-__expf(tdecay[c]));
    float d = __expf(-q);
    float A = 0.f, B = 0.f;
    int base = s * L_CHUNK;
    for (int j = 0; j < L_CHUNK; j++) {
        size_t off = (size_t)(base + j) * C_DIM + c;
        float e = __expf(g_k[off]);
        float vv = g_v[off];
        A = d * A + e * vv;
        B = d * B + e;
    }
    g_carryA[s * C_DIM + c] = A;
    g_carryB[s * C_DIM + c] = B;
}

__global__ void wkv_pass2(const float* __restrict__ tdecay)
{
    int c = blockIdx.x * 256 + threadIdx.x;
    float q = __expf(-__expf(tdecay[c]));
    float dL = __expf(-q * (float)L_CHUNK);
    float A = 0.f, B = 0.f;
    for (int s = 0; s < S_CHUNKS; s++) {
        g_scanA[s * C_DIM + c] = A;
        g_scanB[s * C_DIM + c] = B;
        A = dL * A + g_carryA[s * C_DIM + c];
        B = dL * B + g_carryB[s * C_DIM + c];
    }
}

__global__ void wkv_pass3(const float* __restrict__ tdecay,
                          const float* __restrict__ tfirst)
{
    int s = blockIdx.x >> 3;
    int c = ((blockIdx.x & 7) << 8) + threadIdx.x;
    float q = __expf(-__expf(tdecay[c]));
    float d = __expf(-q);
    float eu = __expf(tfirst[c]);
    float A = g_scanA[s * C_DIM + c];
    float B = g_scanB[s * C_DIM + c];
    int base = s * L_CHUNK;
    for (int j = 0; j < L_CHUNK; j++) {
        size_t off = (size_t)(base + j) * C_DIM + c;
        float kk = g_k[off];
        float vv = g_v[off];
        float rr = g_r[off];
        float e = __expf(kk);
        float eue = eu * e;
        float wkv = (A + eue * vv) / (B + eue);
        float sr = 1.f / (1.f + __expf(-rr));
        float g = sr * wkv;
        f16 h = __float2half_rn(g);
        g_gh[off] = h;
        g_gl[off] = __float2half_rn(g - __half2float(h));
        A = d * A + e * vv;
        B = d * B + e;
    }
}

// ===================== launch =====================
extern "C" void kernel_launch(void* const* d_in, const int* in_sizes, int n_in,
                              void* d_out, int out_size)
{
    const float* x  = (const float*)d_in[0];
    const float* tf = (const float*)d_in[1];
    const float* td = (const float*)d_in[2];
    const float* mk = (const float*)d_in[3];
    const float* mv = (const float*)d_in[4];
    const float* mr = (const float*)d_in[5];
    const float* Wk = (const float*)d_in[6];
    const float* Wv = (const float*)d_in[7];
    const float* Wr = (const float*)d_in[8];
    const float* Wo = (const float*)d_in[9];
    float* out = (float*)d_out;

    cudaFuncSetAttribute(gemm_qkv, cudaFuncAttributeMaxDynamicSharedMemorySize, SMEM_TOTAL);
    cudaFuncSetAttribute(gemm_out, cudaFuncAttributeMaxDynamicSharedMemorySize, SMEM_TOTAL);

    // 1: mix + split
    mix_split<<<(T_DIM * C_DIM / 4) / 256, 256>>>(x, mk, mv, mr);
    // 2,3: weight transpose
    dim3 wgrid(C_DIM / 32, K_DIM / 32, 2), wblk(32, 8);
    wsplit_pair<<<wgrid, wblk>>>(Wk, Wv, 0);
    wsplit_pair<<<wgrid, wblk>>>(Wr, Wo, 2);

    // 4: fused k/v/r projections (profiled launch)
    dim3 gqkv(C_DIM / 128, T_DIM / 128, 3);
    gemm_qkv<<<gqkv, 512, SMEM_TOTAL>>>();

    // 5-7: WKV scan + gate
    wkv_pass1<<<S_CHUNKS * (C_DIM / 256), 256>>>(td);
    wkv_pass2<<<C_DIM / 256, 256>>>(td);
    wkv_pass3<<<S_CHUNKS * (C_DIM / 256), 256>>>(td, tf);

    // 8: output projection
    dim3 go(C_DIM / 128, T_DIM / 128);
    gemm_out<<<go, 512, SMEM_TOTAL>>>(out);
}

// round 6
// speedup vs baseline: 3.2696x; 1.0271x over previous
#include <cuda_runtime.h>
#include <cuda_fp16.h>
#include <cstdint>

#define T_DIM  4096
#define C_DIM  2048
#define K_DIM  2048
#define S_CHUNKS 32
#define L_CHUNK  128

#define KTILE  64
#define NKT    (K_DIM / KTILE)        // 32
#define ROWB   144                    // padded row bytes (72 fp16)
#define SECT_A (128 * ROWB)           // 18432 (Ah or Al section)
#define SECT_B (256 * ROWB)           // 36864 (B section, 256 n-rows)
#define STAGE_BYTES (2 * SECT_A + SECT_B)   // 73728
#define NSTAGE 3
#define SMEM_TOTAL (NSTAGE * STAGE_BYTES)   // 221184 (216KB)

typedef __half f16;

// ===================== PTX helpers =====================
__device__ __forceinline__ uint32_t smem_u32(const void* p) {
    uint32_t a;
    asm("{ .reg .u64 t; cvta.to.shared.u64 t, %1; cvt.u32.u64 %0, t; }" : "=r"(a) : "l"(p));
    return a;
}
__device__ __forceinline__ void cp16(uint32_t smem, const void* g) {
    asm volatile("cp.async.cg.shared.global [%0], [%1], 16;" :: "r"(smem), "l"(g));
}
#define CP_COMMIT() asm volatile("cp.async.commit_group;" ::: "memory")
#define CP_WAIT(n)  asm volatile("cp.async.wait_group %0;" :: "n"(n) : "memory")

__device__ __forceinline__ void ldsm4(uint32_t& r0, uint32_t& r1, uint32_t& r2, uint32_t& r3,
                                      uint32_t addr) {
    asm volatile("ldmatrix.sync.aligned.m8n8.x4.shared.b16 {%0,%1,%2,%3}, [%4];"
                 : "=r"(r0), "=r"(r1), "=r"(r2), "=r"(r3) : "r"(addr));
}
__device__ __forceinline__ void mma16816(float& c0, float& c1, float& c2, float& c3,
                                         uint32_t a0, uint32_t a1, uint32_t a2, uint32_t a3,
                                         uint32_t b0, uint32_t b1) {
    asm volatile("mma.sync.aligned.m16n8k16.row.col.f32.f16.f16.f32 "
                 "{%0,%1,%2,%3}, {%4,%5,%6,%7}, {%8,%9}, {%0,%1,%2,%3};"
                 : "+f"(c0), "+f"(c1), "+f"(c2), "+f"(c3)
                 : "r"(a0), "r"(a1), "r"(a2), "r"(a3), "r"(b0), "r"(b1));
}

// ===================== scratch =====================
__device__ float g_k[T_DIM * C_DIM];
__device__ float g_v[T_DIM * C_DIM];
__device__ float g_r[T_DIM * C_DIM];
__device__ float g_carryA[S_CHUNKS * C_DIM];
__device__ float g_carryB[S_CHUNKS * C_DIM];
__device__ float g_scanA[S_CHUNKS * C_DIM];
__device__ float g_scanB[S_CHUNKS * C_DIM];

__device__ f16 g_axh[3][T_DIM * K_DIM];
__device__ f16 g_axl[3][T_DIM * K_DIM];
__device__ f16 g_wt[4][C_DIM * K_DIM];
__device__ f16 g_gh[T_DIM * C_DIM];
__device__ f16 g_gl[T_DIM * C_DIM];

// ===================== pre-pass: mix + fp16 hi/lo split =====================
__global__ void mix_split(const float* __restrict__ x, const float* __restrict__ mk,
                          const float* __restrict__ mv, const float* __restrict__ mr)
{
    int idx = blockIdx.x * 256 + threadIdx.x;
    int m  = idx >> 9;
    int c4 = (idx & 511) << 2;
    size_t off = (size_t)m * C_DIM + c4;
    float4 xc = *(const float4*)(x + off);
    float4 xp = make_float4(0.f, 0.f, 0.f, 0.f);
    if (m > 0) xp = *(const float4*)(x + off - C_DIM);
    const float* mixes[3] = { mk, mv, mr };
#pragma unroll
    for (int p = 0; p < 3; p++) {
        float4 mx = *(const float4*)(mixes[p] + c4);
        float a[4];
        a[0] = xc.x * mx.x + xp.x * (1.f - mx.x);
        a[1] = xc.y * mx.y + xp.y * (1.f - mx.y);
        a[2] = xc.z * mx.z + xp.z * (1.f - mx.z);
        a[3] = xc.w * mx.w + xp.w * (1.f - mx.w);
        f16 h[4], l[4];
#pragma unroll
        for (int q = 0; q < 4; q++) {
            h[q] = __float2half_rn(a[q]);
            l[q] = __float2half_rn(a[q] - __half2float(h[q]));
        }
        *(uint2*)(&g_axh[p][off]) = *(uint2*)h;
        *(uint2*)(&g_axl[p][off]) = *(uint2*)l;
    }
}

// ===================== pre-pass: weight transpose to fp16 [N,K] =====================
__global__ void wsplit_pair(const float* __restrict__ W0, const float* __restrict__ W1,
                            int base)
{
    __shared__ float t[32][33];
    const float* W = (blockIdx.z == 0) ? W0 : W1;
    int which = base + blockIdx.z;
    int n0 = blockIdx.x * 32, k0 = blockIdx.y * 32;
    int tx = threadIdx.x, ty = threadIdx.y;
#pragma unroll
    for (int i = 0; i < 32; i += 8)
        t[ty + i][tx] = W[(size_t)(k0 + ty + i) * C_DIM + n0 + tx];
    __syncthreads();
#pragma unroll
    for (int i = 0; i < 32; i += 8)
        g_wt[which][(size_t)(n0 + ty + i) * K_DIM + k0 + tx] =
            __float2half_rn(t[tx][ty + i]);
}

// ===================== HMMA GEMM (fp16 2-product, CTA 128x256) =====================
__device__ __forceinline__ void load_stage(
    uint32_t sb, int slot, int kt, int m0, int n0, int tid,
    const f16* __restrict__ Ah, const f16* __restrict__ Al, const f16* __restrict__ B)
{
    const int k0 = kt * KTILE;
    uint32_t base = sb + slot * STAGE_BYTES;
#pragma unroll
    for (int t = 0; t < 8; t++) {
        int id = tid + t * 512;             // 0..4095
        int ch = (id & 7) << 3;             // fp16 units: 0,8,...,56
        uint32_t so;
        const f16* src;
        int grow;
        if (id < 2048) {                    // Ah (0..1023) / Al (1024..2047)
            int sect = id >> 10;
            int row  = (id & 1023) >> 3;
            so   = base + sect * SECT_A + row * ROWB + ch * 2;
            src  = sect ? Al : Ah;
            grow = m0 + row;
        } else {                            // B (2048..4095), 256 rows
            int row = (id - 2048) >> 3;
            so   = base + 2 * SECT_A + row * ROWB + ch * 2;
            src  = B;
            grow = n0 + row;
        }
        cp16(so, src + (size_t)grow * K_DIM + k0 + ch);
    }
    CP_COMMIT();
}

__device__ __forceinline__ void gemm_body(
    const f16* __restrict__ Ah, const f16* __restrict__ Al,
    const f16* __restrict__ B, float* __restrict__ Cout)
{
    extern __shared__ __align__(128) char smem[];
    uint32_t sb = smem_u32(smem);
    const int tid = threadIdx.x;
    const int wid = tid >> 5, lane = tid & 31;
    const int warp_m = wid >> 2;           // 0..3 (32 rows each)
    const int warp_n = wid & 3;            // 0..3 (64 cols each)
    const int m0 = blockIdx.y * 128;
    const int n0 = blockIdx.x * 256;

    float acc[2][8][4];
#pragma unroll
    for (int i = 0; i < 2; i++)
#pragma unroll
        for (int j = 0; j < 8; j++)
#pragma unroll
            for (int q = 0; q < 4; q++) acc[i][j][q] = 0.f;

    load_stage(sb, 0, 0, m0, n0, tid, Ah, Al, B);
    load_stage(sb, 1, 1, m0, n0, tid, Ah, Al, B);

    const uint32_t lrow = lane & 15;
    const uint32_t lcol = (lane >> 4) << 3;

    for (int kt = 0; kt < NKT; kt++) {
        const int s = kt % NSTAGE;
        CP_WAIT(1);
        __syncthreads();
        if (kt + 2 < NKT)
            load_stage(sb, (kt + 2) % NSTAGE, kt + 2, m0, n0, tid, Ah, Al, B);
        else
            CP_COMMIT();

        uint32_t stage = sb + s * STAGE_BYTES;
#pragma unroll
        for (int kk = 0; kk < 4; kk++) {
            uint32_t coff = (kk * 16 + lcol) * 2;
            uint32_t abase = stage + (warp_m * 32 + lrow) * ROWB + coff;
            uint32_t bbase = stage + 2 * SECT_A + (warp_n * 64 + lrow) * ROWB + coff;

            uint32_t ah[2][4], al[2][4], b[16];
#pragma unroll
            for (int mi = 0; mi < 2; mi++) {
                uint32_t ra = abase + mi * 16 * ROWB;
                ldsm4(ah[mi][0], ah[mi][1], ah[mi][2], ah[mi][3], ra);
                ldsm4(al[mi][0], al[mi][1], al[mi][2], al[mi][3], ra + SECT_A);
            }
#pragma unroll
            for (int q = 0; q < 4; q++)
                ldsm4(b[q * 4], b[q * 4 + 1], b[q * 4 + 2], b[q * 4 + 3],
                      bbase + q * 16 * ROWB);

#pragma unroll
            for (int mi = 0; mi < 2; mi++) {
#pragma unroll
                for (int nt = 0; nt < 8; nt++) {
                    int i0 = (nt >> 1) * 4 + (nt & 1);
                    float* c = acc[mi][nt];
                    mma16816(c[0], c[1], c[2], c[3],
                             ah[mi][0], ah[mi][1], ah[mi][2], ah[mi][3],
                             b[i0], b[i0 + 2]);
                    mma16816(c[0], c[1], c[2], c[3],
                             al[mi][0], al[mi][1], al[mi][2], al[mi][3],
                             b[i0], b[i0 + 2]);
                }
            }
        }
    }

    const int er = lane >> 2;
    const int ec = (lane & 3) * 2;
#pragma unroll
    for (int mi = 0; mi < 2; mi++) {
#pragma unroll
        for (int nt = 0; nt < 8; nt++) {
            int r = m0 + warp_m * 32 + mi * 16 + er;
            int c = n0 + warp_n * 64 + nt * 8 + ec;
            float* c0 = Cout + (size_t)r * 2048 + c;
            *(float2*)c0              = make_float2(acc[mi][nt][0], acc[mi][nt][1]);
            *(float2*)(c0 + 8 * 2048) = make_float2(acc[mi][nt][2], acc[mi][nt][3]);
        }
    }
}

__global__ void __launch_bounds__(512) gemm_qkv()
{
    int p = blockIdx.z;
    float* C = (p == 0) ? g_k : (p == 1) ? g_v : g_r;
    gemm_body(g_axh[p], g_axl[p], g_wt[p], C);
}

__global__ void __launch_bounds__(512) gemm_out(float* __restrict__ out)
{
    gemm_body(g_gh, g_gl, g_wt[3], out);
}

// ===================== WKV chunked scan =====================
__global__ void wkv_pass1(const float* __restrict__ tdecay)
{
    int s = blockIdx.x >> 3;
    int c = ((blockIdx.x & 7) << 8) + threadIdx.x;
    float q = __expf(-__expf(tdecay[c]));
    float d = __expf(-q);
    float A = 0.f, B = 0.f;
    int base = s * L_CHUNK;
    for (int j = 0; j < L_CHUNK; j++) {
        size_t off = (size_t)(base + j) * C_DIM + c;
        float e = __expf(g_k[off]);
        float vv = g_v[off];
        A = d * A + e * vv;
        B = d * B + e;
    }
    g_carryA[s * C_DIM + c] = A;
    g_carryB[s * C_DIM + c] = B;
}

__global__ void wkv_pass2(const float* __restrict__ tdecay)
{
    int c = blockIdx.x * 256 + threadIdx.x;
    float q = __expf(-__expf(tdecay[c]));
    float dL = __expf(-q * (float)L_CHUNK);
    float A = 0.f, B = 0.f;
    for (int s = 0; s < S_CHUNKS; s++) {
        g_scanA[s * C_DIM + c] = A;
        g_scanB[s * C_DIM + c] = B;
        A = dL * A + g_carryA[s * C_DIM + c];
        B = dL * B + g_carryB[s * C_DIM + c];
    }
}

__global__ void wkv_pass3(const float* __restrict__ tdecay,
                          const float* __restrict__ tfirst)
{
    int s = blockIdx.x >> 3;
    int c = ((blockIdx.x & 7) << 8) + threadIdx.x;
    float q = __expf(-__expf(tdecay[c]));
    float d = __expf(-q);
    float eu = __expf(tfirst[c]);
    float A = g_scanA[s * C_DIM + c];
    float B = g_scanB[s * C_DIM + c];
    int base = s * L_CHUNK;
    for (int j = 0; j < L_CHUNK; j++) {
        size_t off = (size_t)(base + j) * C_DIM + c;
        float kk = g_k[off];
        float vv = g_v[off];
        float rr = g_r[off];
        float e = __expf(kk);
        float eue = eu * e;
        float wkv = (A + eue * vv) / (B + eue);
        float sr = 1.f / (1.f + __expf(-rr));
        float g = sr * wkv;
        f16 h = __float2half_rn(g);
        g_gh[off] = h;
        g_gl[off] = __float2half_rn(g - __half2float(h));
        A = d * A + e * vv;
        B = d * B + e;
    }
}

// ===================== launch =====================
extern "C" void kernel_launch(void* const* d_in, const int* in_sizes, int n_in,
                              void* d_out, int out_size)
{
    const float* x  = (const float*)d_in[0];
    const float* tf = (const float*)d_in[1];
    const float* td = (const float*)d_in[2];
    const float* mk = (const float*)d_in[3];
    const float* mv = (const float*)d_in[4];
    const float* mr = (const float*)d_in[5];
    const float* Wk = (const float*)d_in[6];
    const float* Wv = (const float*)d_in[7];
    const float* Wr = (const float*)d_in[8];
    const float* Wo = (const float*)d_in[9];
    float* out = (float*)d_out;

    cudaFuncSetAttribute(gemm_qkv, cudaFuncAttributeMaxDynamicSharedMemorySize, SMEM_TOTAL);
    cudaFuncSetAttribute(gemm_out, cudaFuncAttributeMaxDynamicSharedMemorySize, SMEM_TOTAL);

    // 1: mix + split
    mix_split<<<(T_DIM * C_DIM / 4) / 256, 256>>>(x, mk, mv, mr);
    // 2,3: weight transpose
    dim3 wgrid(C_DIM / 32, K_DIM / 32, 2), wblk(32, 8);
    wsplit_pair<<<wgrid, wblk>>>(Wk, Wv, 0);
    wsplit_pair<<<wgrid, wblk>>>(Wr, Wo, 2);

    // 4: fused k/v/r projections (profiled launch)
    dim3 gqkv(C_DIM / 256, T_DIM / 128, 3);
    gemm_qkv<<<gqkv, 512, SMEM_TOTAL>>>();

    // 5-7: WKV scan + gate
    wkv_pass1<<<S_CHUNKS * (C_DIM / 256), 256>>>(td);
    wkv_pass2<<<C_DIM / 256, 256>>>(td);
    wkv_pass3<<<S_CHUNKS * (C_DIM / 256), 256>>>(td, tf);

    // 8: output projection
    dim3 go(C_DIM / 256, T_DIM / 128);
    gemm_out<<<go, 512, SMEM_TOTAL>>>(out);
}

// round 7
// speedup vs baseline: 5.4423x; 1.6645x over previous
#include <cuda_runtime.h>
#include <cuda_fp16.h>
#include <cstdint>

#define T_DIM  4096
#define C_DIM  2048
#define K_DIM  2048
#define S_CHUNKS 32
#define L_CHUNK  128

#define KTILE  64
#define NKT    (K_DIM / KTILE)        // 32
#define ROWB   144                    // padded row bytes (72 fp16)
#define SECT_A (128 * ROWB)           // 18432
#define SECT_B (256 * ROWB)           // 36864
#define STAGE_BYTES (SECT_A + SECT_B) // 55296
#define NSTAGE 4
#define SMEM_TOTAL (NSTAGE * STAGE_BYTES)   // 221184 (216KB)

typedef __half f16;

// ===================== PTX helpers =====================
__device__ __forceinline__ uint32_t smem_u32(const void* p) {
    uint32_t a;
    asm("{ .reg .u64 t; cvta.to.shared.u64 t, %1; cvt.u32.u64 %0, t; }" : "=r"(a) : "l"(p));
    return a;
}
__device__ __forceinline__ void cp16(uint32_t smem, const void* g) {
    asm volatile("cp.async.cg.shared.global [%0], [%1], 16;" :: "r"(smem), "l"(g));
}
#define CP_COMMIT() asm volatile("cp.async.commit_group;" ::: "memory")
#define CP_WAIT(n)  asm volatile("cp.async.wait_group %0;" :: "n"(n) : "memory")

__device__ __forceinline__ void ldsm4(uint32_t& r0, uint32_t& r1, uint32_t& r2, uint32_t& r3,
                                      uint32_t addr) {
    asm volatile("ldmatrix.sync.aligned.m8n8.x4.shared.b16 {%0,%1,%2,%3}, [%4];"
                 : "=r"(r0), "=r"(r1), "=r"(r2), "=r"(r3) : "r"(addr));
}
__device__ __forceinline__ void mma16816(float& c0, float& c1, float& c2, float& c3,
                                         uint32_t a0, uint32_t a1, uint32_t a2, uint32_t a3,
                                         uint32_t b0, uint32_t b1) {
    asm volatile("mma.sync.aligned.m16n8k16.row.col.f32.f16.f16.f32 "
                 "{%0,%1,%2,%3}, {%4,%5,%6,%7}, {%8,%9}, {%0,%1,%2,%3};"
                 : "+f"(c0), "+f"(c1), "+f"(c2), "+f"(c3)
                 : "r"(a0), "r"(a1), "r"(a2), "r"(a3), "r"(b0), "r"(b1));
}

// ===================== scratch =====================
__device__ float g_k[T_DIM * C_DIM];
__device__ float g_v[T_DIM * C_DIM];
__device__ float g_r[T_DIM * C_DIM];
__device__ float g_carryA[S_CHUNKS * C_DIM];
__device__ float g_carryB[S_CHUNKS * C_DIM];
__device__ float g_scanA[S_CHUNKS * C_DIM];
__device__ float g_scanB[S_CHUNKS * C_DIM];

__device__ f16 g_ax[3][T_DIM * K_DIM];   // mixed activations (fp16)
__device__ f16 g_wt[4][C_DIM * K_DIM];   // W^T [N,K] fp16
__device__ f16 g_g[T_DIM * C_DIM];       // gated output (fp16)

// ===================== pre-pass: mix to fp16 =====================
__global__ void mix_split(const float* __restrict__ x, const float* __restrict__ mk,
                          const float* __restrict__ mv, const float* __restrict__ mr)
{
    int idx = blockIdx.x * 256 + threadIdx.x;
    int m  = idx >> 9;
    int c4 = (idx & 511) << 2;
    size_t off = (size_t)m * C_DIM + c4;
    float4 xc = *(const float4*)(x + off);
    float4 xp = make_float4(0.f, 0.f, 0.f, 0.f);
    if (m > 0) xp = *(const float4*)(x + off - C_DIM);
    const float* mixes[3] = { mk, mv, mr };
#pragma unroll
    for (int p = 0; p < 3; p++) {
        float4 mx = *(const float4*)(mixes[p] + c4);
        f16 h[4];
        h[0] = __float2half_rn(xc.x * mx.x + xp.x * (1.f - mx.x));
        h[1] = __float2half_rn(xc.y * mx.y + xp.y * (1.f - mx.y));
        h[2] = __float2half_rn(xc.z * mx.z + xp.z * (1.f - mx.z));
        h[3] = __float2half_rn(xc.w * mx.w + xp.w * (1.f - mx.w));
        *(uint2*)(&g_ax[p][off]) = *(uint2*)h;
    }
}

// ===================== pre-pass: weight transpose to fp16 [N,K] =====================
__global__ void wsplit_pair(const float* __restrict__ W0, const float* __restrict__ W1,
                            int base)
{
    __shared__ float t[32][33];
    const float* W = (blockIdx.z == 0) ? W0 : W1;
    int which = base + blockIdx.z;
    int n0 = blockIdx.x * 32, k0 = blockIdx.y * 32;
    int tx = threadIdx.x, ty = threadIdx.y;
#pragma unroll
    for (int i = 0; i < 32; i += 8)
        t[ty + i][tx] = W[(size_t)(k0 + ty + i) * C_DIM + n0 + tx];
    __syncthreads();
#pragma unroll
    for (int i = 0; i < 32; i += 8)
        g_wt[which][(size_t)(n0 + ty + i) * K_DIM + k0 + tx] =
            __float2half_rn(t[tx][ty + i]);
}

// ===================== HMMA GEMM (single fp16 product, CTA 128x256) =====================
__device__ __forceinline__ void load_stage(
    uint32_t sb, int slot, int kt, int m0, int n0, int tid,
    const f16* __restrict__ A, const f16* __restrict__ B)
{
    const int k0 = kt * KTILE;
    uint32_t base = sb + slot * STAGE_BYTES;
#pragma unroll
    for (int t = 0; t < 6; t++) {
        int id = tid + t * 512;             // 0..3071
        int ch = (id & 7) << 3;             // fp16 units: 0,8,...,56
        uint32_t so;
        const f16* src;
        int grow;
        if (id < 1024) {                    // A: 128 rows
            int row = id >> 3;
            so   = base + row * ROWB + ch * 2;
            src  = A;
            grow = m0 + row;
        } else {                            // B: 256 rows
            int row = (id - 1024) >> 3;
            so   = base + SECT_A + row * ROWB + ch * 2;
            src  = B;
            grow = n0 + row;
        }
        cp16(so, src + (size_t)grow * K_DIM + k0 + ch);
    }
    CP_COMMIT();
}

__device__ __forceinline__ void gemm_body(
    const f16* __restrict__ A, const f16* __restrict__ B, float* __restrict__ Cout)
{
    extern __shared__ __align__(128) char smem[];
    uint32_t sb = smem_u32(smem);
    const int tid = threadIdx.x;
    const int wid = tid >> 5, lane = tid & 31;
    const int warp_m = wid >> 2;           // 0..3 (32 rows each)
    const int warp_n = wid & 3;            // 0..3 (64 cols each)
    const int m0 = blockIdx.y * 128;
    const int n0 = blockIdx.x * 256;

    float acc[2][8][4];
#pragma unroll
    for (int i = 0; i < 2; i++)
#pragma unroll
        for (int j = 0; j < 8; j++)
#pragma unroll
            for (int q = 0; q < 4; q++) acc[i][j][q] = 0.f;

    load_stage(sb, 0, 0, m0, n0, tid, A, B);
    load_stage(sb, 1, 1, m0, n0, tid, A, B);
    load_stage(sb, 2, 2, m0, n0, tid, A, B);

    const uint32_t lrow = lane & 15;
    const uint32_t lcol = (lane >> 4) << 3;

    for (int kt = 0; kt < NKT; kt++) {
        const int s = kt & 3;
        CP_WAIT(2);
        __syncthreads();
        if (kt + 3 < NKT)
            load_stage(sb, (kt + 3) & 3, kt + 3, m0, n0, tid, A, B);
        else
            CP_COMMIT();

        uint32_t stage = sb + s * STAGE_BYTES;
#pragma unroll
        for (int kk = 0; kk < 4; kk++) {
            uint32_t coff = (kk * 16 + lcol) * 2;
            uint32_t abase = stage + (warp_m * 32 + lrow) * ROWB + coff;
            uint32_t bbase = stage + SECT_A + (warp_n * 64 + lrow) * ROWB + coff;

            uint32_t a[2][4], b[16];
#pragma unroll
            for (int mi = 0; mi < 2; mi++)
                ldsm4(a[mi][0], a[mi][1], a[mi][2], a[mi][3], abase + mi * 16 * ROWB);
#pragma unroll
            for (int q = 0; q < 4; q++)
                ldsm4(b[q * 4], b[q * 4 + 1], b[q * 4 + 2], b[q * 4 + 3],
                      bbase + q * 16 * ROWB);

#pragma unroll
            for (int mi = 0; mi < 2; mi++) {
#pragma unroll
                for (int nt = 0; nt < 8; nt++) {
                    int i0 = (nt >> 1) * 4 + (nt & 1);
                    float* c = acc[mi][nt];
                    mma16816(c[0], c[1], c[2], c[3],
                             a[mi][0], a[mi][1], a[mi][2], a[mi][3],
                             b[i0], b[i0 + 2]);
                }
            }
        }
    }

    const int er = lane >> 2;
    const int ec = (lane & 3) * 2;
#pragma unroll
    for (int mi = 0; mi < 2; mi++) {
#pragma unroll
        for (int nt = 0; nt < 8; nt++) {
            int r = m0 + warp_m * 32 + mi * 16 + er;
            int c = n0 + warp_n * 64 + nt * 8 + ec;
            float* c0 = Cout + (size_t)r * 2048 + c;
            *(float2*)c0              = make_float2(acc[mi][nt][0], acc[mi][nt][1]);
            *(float2*)(c0 + 8 * 2048) = make_float2(acc[mi][nt][2], acc[mi][nt][3]);
        }
    }
}

__global__ void __launch_bounds__(512) gemm_qkv()
{
    int p = blockIdx.z;
    float* C = (p == 0) ? g_k : (p == 1) ? g_v : g_r;
    gemm_body(g_ax[p], g_wt[p], C);
}

__global__ void __launch_bounds__(512) gemm_out(float* __restrict__ out)
{
    gemm_body(g_g, g_wt[3], out);
}

// ===================== WKV chunked scan =====================
__global__ void wkv_pass1(const float* __restrict__ tdecay)
{
    int s = blockIdx.x >> 3;
    int c = ((blockIdx.x & 7) << 8) + threadIdx.x;
    float q = __expf(-__expf(tdecay[c]));
    float d = __expf(-q);
    float A = 0.f, B = 0.f;
    int base = s * L_CHUNK;
    for (int j = 0; j < L_CHUNK; j++) {
        size_t off = (size_t)(base + j) * C_DIM + c;
        float e = __expf(g_k[off]);
        float vv = g_v[off];
        A = d * A + e * vv;
        B = d * B + e;
    }
    g_carryA[s * C_DIM + c] = A;
    g_carryB[s * C_DIM + c] = B;
}

__global__ void wkv_pass2(const float* __restrict__ tdecay)
{
    int c = blockIdx.x * 256 + threadIdx.x;
    float q = __expf(-__expf(tdecay[c]));
    float dL = __expf(-q * (float)L_CHUNK);
    float A = 0.f, B = 0.f;
    for (int s = 0; s < S_CHUNKS; s++) {
        g_scanA[s * C_DIM + c] = A;
        g_scanB[s * C_DIM + c] = B;
        A = dL * A + g_carryA[s * C_DIM + c];
        B = dL * B + g_carryB[s * C_DIM + c];
    }
}

__global__ void wkv_pass3(const float* __restrict__ tdecay,
                          const float* __restrict__ tfirst)
{
    int s = blockIdx.x >> 3;
    int c = ((blockIdx.x & 7) << 8) + threadIdx.x;
    float q = __expf(-__expf(tdecay[c]));
    float d = __expf(-q);
    float eu = __expf(tfirst[c]);
    float A = g_scanA[s * C_DIM + c];
    float B = g_scanB[s * C_DIM + c];
    int base = s * L_CHUNK;
    for (int j = 0; j < L_CHUNK; j++) {
        size_t off = (size_t)(base + j) * C_DIM + c;
        float kk = g_k[off];
        float vv = g_v[off];
        float rr = g_r[off];
        float e = __expf(kk);
        float eue = eu * e;
        float wkv = (A + eue * vv) / (B + eue);
        float sr = 1.f / (1.f + __expf(-rr));
        g_g[off] = __float2half_rn(sr * wkv);
        A = d * A + e * vv;
        B = d * B + e;
    }
}

// ===================== launch =====================
extern "C" void kernel_launch(void* const* d_in, const int* in_sizes, int n_in,
                              void* d_out, int out_size)
{
    const float* x  = (const float*)d_in[0];
    const float* tf = (const float*)d_in[1];
    const float* td = (const float*)d_in[2];
    const float* mk = (const float*)d_in[3];
    const float* mv = (const float*)d_in[4];
    const float* mr = (const float*)d_in[5];
    const float* Wk = (const float*)d_in[6];
    const float* Wv = (const float*)d_in[7];
    const float* Wr = (const float*)d_in[8];
    const float* Wo = (const float*)d_in[9];
    float* out = (float*)d_out;

    cudaFuncSetAttribute(gemm_qkv, cudaFuncAttributeMaxDynamicSharedMemorySize, SMEM_TOTAL);
    cudaFuncSetAttribute(gemm_out, cudaFuncAttributeMaxDynamicSharedMemorySize, SMEM_TOTAL);

    // 1: mix to fp16
    mix_split<<<(T_DIM * C_DIM / 4) / 256, 256>>>(x, mk, mv, mr);
    // 2,3: weight transpose
    dim3 wgrid(C_DIM / 32, K_DIM / 32, 2), wblk(32, 8);
    wsplit_pair<<<wgrid, wblk>>>(Wk, Wv, 0);
    wsplit_pair<<<wgrid, wblk>>>(Wr, Wo, 2);

    // 4: fused k/v/r projections (profiled launch)
    dim3 gqkv(C_DIM / 256, T_DIM / 128, 3);
    gemm_qkv<<<gqkv, 512, SMEM_TOTAL>>>();

    // 5-7: WKV scan + gate
    wkv_pass1<<<S_CHUNKS * (C_DIM / 256), 256>>>(td);
    wkv_pass2<<<C_DIM / 256, 256>>>(td);
    wkv_pass3<<<S_CHUNKS * (C_DIM / 256), 256>>>(td, tf);

    // 8: output projection
    dim3 go(C_DIM / 256, T_DIM / 128);
    gemm_out<<<go, 512, SMEM_TOTAL>>>(out);
}